// round 2
// baseline (speedup 1.0000x reference)
#include <cuda_runtime.h>
#include <math.h>
#include <stdint.h>

// Problem maxima (fixed by the dataset): N=100000, E=1600000, IN=128, H=64
#define MAXN 100000
#define MAXE 1600000
#define HDIM 64

// ---------------- scratch (static device globals; no allocation) -------------
__device__ int    g_deg_in[MAXN];
__device__ int    g_deg_out[MAXN];
__device__ int    g_row_start[MAXN + 1];
__device__ int    g_cursor[MAXN];
__device__ int    g_csr_src[MAXE];
__device__ float  g_norm_src[MAXN];
__device__ float  g_norm_dst[MAXN];
__device__ float  g_bufA[(size_t)MAXN * HDIM];
__device__ float  g_bufB[(size_t)MAXN * HDIM];
__device__ float  g_wv[HDIM];
__device__ float  g_bsum;
__device__ double g_loss;

// ---------------- setup kernels ----------------------------------------------
__global__ void zero_kernel(int n) {
    int i = blockIdx.x * blockDim.x + threadIdx.x;
    if (i < n) { g_deg_in[i] = 0; g_deg_out[i] = 0; g_cursor[i] = 0; }
    if (i == 0) g_loss = 0.0;
}

__global__ void degree_kernel(const int* __restrict__ src,
                              const int* __restrict__ dst, int E) {
    int i = blockIdx.x * blockDim.x + threadIdx.x;
    if (i < E) {
        atomicAdd(&g_deg_out[src[i]], 1);
        atomicAdd(&g_deg_in[dst[i]], 1);
    }
}

__global__ void norm_kernel(int n) {
    int i = blockIdx.x * blockDim.x + threadIdx.x;
    if (i < n) {
        g_norm_src[i] = rsqrtf((float)max(g_deg_out[i], 1));
        g_norm_dst[i] = rsqrtf((float)max(g_deg_in[i], 1));
    }
}

// Single-block exclusive scan of g_deg_in -> g_row_start (N up to 100k).
__global__ void scan_kernel(int n) {
    __shared__ int ssum[1024];
    int t = threadIdx.x;
    int C = (n + 1023) / 1024;
    int lo = t * C;
    int hi = min(lo + C, n);
    int s = 0;
    for (int i = lo; i < hi; i++) s += g_deg_in[i];
    ssum[t] = s;
    __syncthreads();
    // Hillis-Steele inclusive scan over 1024 entries
    for (int off = 1; off < 1024; off <<= 1) {
        int v = (t >= off) ? ssum[t - off] : 0;
        __syncthreads();
        ssum[t] += v;
        __syncthreads();
    }
    int run = (t == 0) ? 0 : ssum[t - 1];
    for (int i = lo; i < hi; i++) { g_row_start[i] = run; run += g_deg_in[i]; }
    if (t == 1023) g_row_start[n] = run;
}

__global__ void scatter_kernel(const int* __restrict__ src,
                               const int* __restrict__ dst, int E) {
    int i = blockIdx.x * blockDim.x + threadIdx.x;
    if (i < E) {
        int d = dst[i];
        int pos = atomicAdd(&g_cursor[d], 1);
        g_csr_src[g_row_start[d] + pos] = src[i];
    }
}

// wv[k] = sum_j Wm[k][j];  bsum = sum_j bm[j]
__global__ void wv_kernel(const float* __restrict__ Wm, const float* __restrict__ bm) {
    int k = threadIdx.x;
    if (k < HDIM) {
        float s = 0.f;
        #pragma unroll 8
        for (int j = 0; j < HDIM; j++) s += Wm[k * HDIM + j];
        g_wv[k] = s;
    }
    if (k == 0) {
        float b = 0.f;
        #pragma unroll 8
        for (int j = 0; j < HDIM; j++) b += bm[j];
        g_bsum = b;
    }
}

// ---------------- GEMM: out[n][j] = norm_src[n] * sum_k X[g(n)][k] * W[k][j] --
// Tile: 64 rows x 64 cols per block of 256 threads; 4x4 register blocking.
template <int K>
__global__ __launch_bounds__(256) void gemm_kernel(
    const float* __restrict__ X, const float* __restrict__ W,
    const int* __restrict__ perm, const float* __restrict__ nsrc,
    float* __restrict__ out, int n)
{
    __shared__ float Xs[64][K + 4];
    const int tid  = threadIdx.x;
    const int row0 = blockIdx.x * 64;
    const int KV   = K / 4;

    // cooperative load of the 64 x K X-tile (fused norm_src scaling, opt perm)
    for (int v = tid; v < 64 * KV; v += 256) {
        int r  = v / KV;
        int kv = v - r * KV;
        int nd = row0 + r;
        float4 val = make_float4(0.f, 0.f, 0.f, 0.f);
        if (nd < n) {
            int g = perm ? __ldg(&perm[nd]) : nd;
            val = __ldg(reinterpret_cast<const float4*>(X) + (size_t)g * KV + kv);
            float s = nsrc[nd];
            val.x *= s; val.y *= s; val.z *= s; val.w *= s;
        }
        *reinterpret_cast<float4*>(&Xs[r][kv * 4]) = val;
    }
    __syncthreads();

    const int cg = (tid & 15) * 4;   // 4 consecutive output cols
    const int rg = (tid >> 4) * 4;   // 4 consecutive rows

    float acc[4][4];
    #pragma unroll
    for (int r = 0; r < 4; r++)
        #pragma unroll
        for (int c = 0; c < 4; c++) acc[r][c] = 0.f;

    const float4* W4 = reinterpret_cast<const float4*>(W);

    #pragma unroll 8
    for (int k0 = 0; k0 < K; k0 += 4) {
        float4 xr[4];
        #pragma unroll
        for (int r = 0; r < 4; r++)
            xr[r] = *reinterpret_cast<const float4*>(&Xs[rg + r][k0]);
        #pragma unroll
        for (int kk = 0; kk < 4; kk++) {
            float4 w = __ldg(&W4[((k0 + kk) * HDIM + cg) >> 2]);
            #pragma unroll
            for (int r = 0; r < 4; r++) {
                float xv = reinterpret_cast<const float*>(&xr[r])[kk];
                acc[r][0] += xv * w.x;
                acc[r][1] += xv * w.y;
                acc[r][2] += xv * w.z;
                acc[r][3] += xv * w.w;
            }
        }
    }

    #pragma unroll
    for (int r = 0; r < 4; r++) {
        int nd = row0 + rg + r;
        if (nd < n) {
            float4 o = make_float4(acc[r][0], acc[r][1], acc[r][2], acc[r][3]);
            *reinterpret_cast<float4*>(&out[(size_t)nd * HDIM + cg]) = o;
        }
    }
}

// ---------------- aggregation: warp per dst node -----------------------------
// tout[n][:] = relu( (sum_{e in-edges(n)} tin[src(e)][:]) * norm_dst[n] + b[:] )
__global__ __launch_bounds__(256) void agg_kernel(
    const float* __restrict__ tin, float* __restrict__ tout,
    const float* __restrict__ b, int n)
{
    int warp = (blockIdx.x * blockDim.x + threadIdx.x) >> 5;
    int lane = threadIdx.x & 31;
    if (warp >= n) return;

    int s0 = g_row_start[warp];
    int s1 = g_row_start[warp + 1];

    float ax = 0.f, ay = 0.f;
    for (int e0 = s0; e0 < s1; e0 += 32) {
        int myE = e0 + lane;
        int mySrc = (myE < s1) ? g_csr_src[myE] : 0;
        int cnt = min(32, s1 - e0);
        for (int j = 0; j < cnt; j++) {
            int s = __shfl_sync(0xffffffffu, mySrc, j);
            float2 v = *reinterpret_cast<const float2*>(tin + (size_t)s * HDIM + lane * 2);
            ax += v.x; ay += v.y;
        }
    }
    float nd = g_norm_dst[warp];
    float2 bb = *reinterpret_cast<const float2*>(b + lane * 2);
    float2 o;
    o.x = fmaxf(fmaf(ax, nd, bb.x), 0.f);
    o.y = fmaxf(fmaf(ay, nd, bb.y), 0.f);
    *reinterpret_cast<float2*>(tout + (size_t)warp * HDIM + lane * 2) = o;
}

// ---------------- score + loss: warp per node --------------------------------
__global__ __launch_bounds__(256) void score_kernel(
    const float* __restrict__ h, const float* __restrict__ labels,
    int label_off, int n)
{
    __shared__ float sw[8];
    int warpInBlock = threadIdx.x >> 5;
    int node = (blockIdx.x * blockDim.x + threadIdx.x) >> 5;
    int lane = threadIdx.x & 31;

    float term = 0.f;
    if (node < n) {
        float2 hv = *reinterpret_cast<const float2*>(h + (size_t)node * HDIM + lane * 2);
        float2 wv = *reinterpret_cast<const float2*>(&g_wv[lane * 2]);
        float p = hv.x * wv.x + hv.y * wv.y;
        #pragma unroll
        for (int o = 16; o; o >>= 1) p += __shfl_down_sync(0xffffffffu, p, o);
        if (lane == 0) {
            float sc = p + g_bsum;
            float y  = labels[label_off + node];
            // logaddexp(0, sc) - sc*y, numerically stable
            term = fmaxf(sc, 0.f) + log1pf(expf(-fabsf(sc))) - sc * y;
        }
    }
    if (lane == 0) sw[warpInBlock] = term;
    __syncthreads();
    if (threadIdx.x == 0) {
        float s = 0.f;
        #pragma unroll
        for (int w = 0; w < 8; w++) s += sw[w];
        atomicAdd(&g_loss, (double)s);
    }
}

__global__ void finalize_kernel(float* __restrict__ out, double inv) {
    out[0] = (float)(g_loss * inv);
}

// ---------------- launch -----------------------------------------------------
extern "C" void kernel_launch(void* const* d_in, const int* in_sizes, int n_in,
                              void* d_out, int out_size) {
    const float* features = (const float*)d_in[0];
    const float* labels   = (const float*)d_in[1];
    const float* W1 = (const float*)d_in[2];
    const float* b1 = (const float*)d_in[3];
    const float* W2 = (const float*)d_in[4];
    const float* b2 = (const float*)d_in[5];
    const float* Wm = (const float*)d_in[6];
    const float* bm = (const float*)d_in[7];
    const int* src  = (const int*)d_in[8];
    const int* dst  = (const int*)d_in[9];
    const int* perm = (const int*)d_in[10];

    int E = in_sizes[8];
    int n = in_sizes[10];

    float* bufA; float* bufB; float* nsrc;
    cudaGetSymbolAddress((void**)&bufA, g_bufA);
    cudaGetSymbolAddress((void**)&bufB, g_bufB);
    cudaGetSymbolAddress((void**)&nsrc, g_norm_src);

    int nb256  = (n + 255) / 256;
    int eb256  = (E + 255) / 256;
    int gemmB  = (n + 63) / 64;
    int warpB  = (n + 7) / 8;   // 8 warps (nodes) per 256-thread block

    zero_kernel<<<nb256, 256>>>(n);
    degree_kernel<<<eb256, 256>>>(src, dst, E);
    norm_kernel<<<nb256, 256>>>(n);
    scan_kernel<<<1, 1024>>>(n);
    scatter_kernel<<<eb256, 256>>>(src, dst, E);
    wv_kernel<<<1, 64>>>(Wm, bm);

    for (int enc = 0; enc < 2; enc++) {
        const int* p = enc ? perm : nullptr;
        gemm_kernel<128><<<gemmB, 256>>>(features, W1, p, nsrc, bufA, n);
        agg_kernel<<<warpB, 256>>>(bufA, bufB, b1, n);
        gemm_kernel<64><<<gemmB, 256>>>(bufB, W2, nullptr, nsrc, bufA, n);
        agg_kernel<<<warpB, 256>>>(bufA, bufB, b2, n);
        score_kernel<<<warpB, 256>>>(bufB, labels, enc * n, n);
    }

    finalize_kernel<<<1, 1>>>((float*)d_out, 0.5 / (double)n);
}

// round 3
// speedup vs baseline: 1.0803x; 1.0803x over previous
#include <cuda_runtime.h>
#include <cuda_fp16.h>
#include <math.h>
#include <stdint.h>

// Problem maxima (fixed by the dataset): N=100000, E=1600000, IN=128, H=64
#define MAXN 100000
#define MAXE 1600000
#define HDIM 64

typedef unsigned long long u64;

// ---------------- scratch (static device globals; no allocation) -------------
__device__ int     g_deg_in[MAXN];
__device__ int     g_deg_out[MAXN];
__device__ int     g_row_start[MAXN + 1];
__device__ int     g_cursor[MAXN];
__device__ int     g_csr_src[MAXE];
__device__ int     g_bsums[128];
__device__ float   g_norm_src[MAXN];
__device__ float   g_norm_dst[MAXN];
__device__ __half2 g_bufAh[(size_t)MAXN * (HDIM / 2)];   // gemm out (fp16), agg in
__device__ float   g_bufB[(size_t)MAXN * HDIM];          // agg out (fp32), gemm in
__device__ float   g_wv[HDIM];
__device__ float   g_bsum;
__device__ double  g_loss;

// ---------------- f32x2 helpers (Blackwell packed FMA) ------------------------
__device__ __forceinline__ u64 pack2(float x) {
    u64 r; asm("mov.b64 %0, {%1, %1};" : "=l"(r) : "f"(x)); return r;
}
__device__ __forceinline__ void ffma2(u64& d, u64 a, u64 b) {
    asm("fma.rn.f32x2 %0, %1, %2, %0;" : "+l"(d) : "l"(a), "l"(b));
}
__device__ __forceinline__ float2 unpack2(u64 v) {
    float2 f; asm("mov.b64 {%0, %1}, %2;" : "=f"(f.x), "=f"(f.y) : "l"(v)); return f;
}

// ---------------- setup kernels ----------------------------------------------
__global__ void zero_kernel(int n, int E) {
    int i = blockIdx.x * blockDim.x + threadIdx.x;
    if (i < n) { g_deg_in[i] = 0; g_deg_out[i] = 0; g_cursor[i] = 0; }
    if (i == 0) { g_loss = 0.0; g_row_start[n] = E; }
}

__global__ void degree_kernel(const int* __restrict__ src,
                              const int* __restrict__ dst, int E) {
    int i = blockIdx.x * blockDim.x + threadIdx.x;
    if (i < E) {
        atomicAdd(&g_deg_out[src[i]], 1);
        atomicAdd(&g_deg_in[dst[i]], 1);
    }
}

__global__ void norm_kernel(int n) {
    int i = blockIdx.x * blockDim.x + threadIdx.x;
    if (i < n) {
        g_norm_src[i] = rsqrtf((float)max(g_deg_out[i], 1));
        g_norm_dst[i] = rsqrtf((float)max(g_deg_in[i], 1));
    }
}

// Phase 1: per-block (1024 elems) local exclusive scan + block total.
__global__ __launch_bounds__(256) void scan1_kernel(int n) {
    __shared__ int warp_tot[8];
    int b = blockIdx.x, t = threadIdx.x;
    int base = b * 1024 + t * 4;
    int d0 = (base + 0 < n) ? g_deg_in[base + 0] : 0;
    int d1 = (base + 1 < n) ? g_deg_in[base + 1] : 0;
    int d2 = (base + 2 < n) ? g_deg_in[base + 2] : 0;
    int d3 = (base + 3 < n) ? g_deg_in[base + 3] : 0;
    int tot = d0 + d1 + d2 + d3;

    int lane = t & 31, w = t >> 5;
    int inc = tot;
    #pragma unroll
    for (int off = 1; off < 32; off <<= 1) {
        int u = __shfl_up_sync(0xffffffffu, inc, off);
        if (lane >= off) inc += u;
    }
    if (lane == 31) warp_tot[w] = inc;
    __syncthreads();
    int woff = 0;
    #pragma unroll
    for (int i = 0; i < 8; i++) if (i < w) woff += warp_tot[i];
    int excl = woff + inc - tot;
    if (base + 0 < n) g_row_start[base + 0] = excl;
    if (base + 1 < n) g_row_start[base + 1] = excl + d0;
    if (base + 2 < n) g_row_start[base + 2] = excl + d0 + d1;
    if (base + 3 < n) g_row_start[base + 3] = excl + d0 + d1 + d2;
    if (t == 255) g_bsums[b] = woff + inc;   // block total
}

// Phase 2: each block adds the prefix of prior block totals (redundant loop).
__global__ __launch_bounds__(256) void scan2_kernel(int n) {
    int b = blockIdx.x, t = threadIdx.x;
    int off = 0;
    for (int i = 0; i < b; i++) off += g_bsums[i];   // <=97 broadcast loads
    int base = b * 1024 + t * 4;
    #pragma unroll
    for (int j = 0; j < 4; j++)
        if (base + j < n) g_row_start[base + j] += off;
}

__global__ void scatter_kernel(const int* __restrict__ src,
                               const int* __restrict__ dst, int E) {
    int i = blockIdx.x * blockDim.x + threadIdx.x;
    if (i < E) {
        int d = dst[i];
        int pos = atomicAdd(&g_cursor[d], 1);
        g_csr_src[g_row_start[d] + pos] = src[i];
    }
}

// wv[k] = sum_j Wm[k][j];  bsum = sum_j bm[j]
__global__ void wv_kernel(const float* __restrict__ Wm, const float* __restrict__ bm) {
    int k = threadIdx.x;
    if (k < HDIM) {
        float s = 0.f;
        #pragma unroll 8
        for (int j = 0; j < HDIM; j++) s += Wm[k * HDIM + j];
        g_wv[k] = s;
    }
    if (k == 0) {
        float b = 0.f;
        #pragma unroll 8
        for (int j = 0; j < HDIM; j++) b += bm[j];
        g_bsum = b;
    }
}

// ---------------- GEMM: out[n][j] = half( norm_src[n] * sum_k X[g(n)][k]*W[k][j] )
// Tile: 128 rows x 64 cols per 256-thread block; thread tile 4 rows x 8 cols.
// Inner product uses Blackwell fma.rn.f32x2 (column-pair packed accumulators).
template <int K>
__global__ __launch_bounds__(256) void gemm_kernel(
    const float* __restrict__ X, const float* __restrict__ W,
    const int* __restrict__ perm, const float* __restrict__ nsrc,
    __half2* __restrict__ out, int n)
{
    extern __shared__ float smemf[];
    const int XS_STRIDE = K + 4;          // multiple of 4 -> float4-aligned rows
    const int WS_STRIDE = 68;
    float* Xs = smemf;                    // [128][K+4]
    float* Ws = smemf + 128 * XS_STRIDE;  // [K][68]

    const int tid  = threadIdx.x;
    const int row0 = blockIdx.x * 128;
    const int KV   = K / 4;

    // Stage X tile (fused norm_src scaling + optional permutation gather)
    const float4* X4 = reinterpret_cast<const float4*>(X);
    for (int v = tid; v < 128 * KV; v += 256) {
        int r  = v / KV;
        int kv = v - r * KV;
        int nd = row0 + r;
        float4 val = make_float4(0.f, 0.f, 0.f, 0.f);
        if (nd < n) {
            int g = perm ? __ldg(&perm[nd]) : nd;
            val = __ldg(X4 + (size_t)g * KV + kv);
            float s = nsrc[nd];
            val.x *= s; val.y *= s; val.z *= s; val.w *= s;
        }
        *reinterpret_cast<float4*>(&Xs[r * XS_STRIDE + kv * 4]) = val;
    }
    // Stage W (K x 64 -> padded 68)
    const float4* W4 = reinterpret_cast<const float4*>(W);
    for (int v = tid; v < K * 16; v += 256) {
        int k  = v >> 4;
        int c4 = v & 15;
        *reinterpret_cast<float4*>(&Ws[k * WS_STRIDE + c4 * 4]) = __ldg(W4 + v);
    }
    __syncthreads();

    const int tcol = tid & 7;
    const int trow = tid >> 3;
    const int cg = tcol * 8;     // 8 consecutive cols
    const int rg = trow * 4;     // 4 consecutive rows

    u64 acc[4][4];
    #pragma unroll
    for (int r = 0; r < 4; r++)
        #pragma unroll
        for (int c = 0; c < 4; c++) acc[r][c] = 0ull;

    #pragma unroll 2
    for (int k0 = 0; k0 < K; k0 += 4) {
        float4 xr[4];
        #pragma unroll
        for (int r = 0; r < 4; r++)
            xr[r] = *reinterpret_cast<const float4*>(&Xs[(rg + r) * XS_STRIDE + k0]);
        #pragma unroll
        for (int kk = 0; kk < 4; kk++) {
            const float* wrow = &Ws[(k0 + kk) * WS_STRIDE + cg];
            ulonglong2 wA = *reinterpret_cast<const ulonglong2*>(wrow);      // cols cg..cg+3
            ulonglong2 wB = *reinterpret_cast<const ulonglong2*>(wrow + 4);  // cols cg+4..cg+7
            #pragma unroll
            for (int r = 0; r < 4; r++) {
                float xv = reinterpret_cast<const float*>(&xr[r])[kk];
                u64 xp = pack2(xv);
                ffma2(acc[r][0], xp, wA.x);
                ffma2(acc[r][1], xp, wA.y);
                ffma2(acc[r][2], xp, wB.x);
                ffma2(acc[r][3], xp, wB.y);
            }
        }
    }

    #pragma unroll
    for (int r = 0; r < 4; r++) {
        int nd = row0 + rg + r;
        if (nd < n) {
            __half2 hv[4];
            #pragma unroll
            for (int c = 0; c < 4; c++) {
                float2 f = unpack2(acc[r][c]);
                hv[c] = __floats2half2_rn(f.x, f.y);
            }
            *reinterpret_cast<uint4*>(&out[(size_t)nd * (HDIM / 2) + tcol * 4]) =
                *reinterpret_cast<const uint4*>(hv);
        }
    }
}

// ---------------- aggregation: warp per dst node -----------------------------
// tout[n][:] = relu( (sum_{in-edges} tin_fp16[src][:]) * norm_dst[n] + b[:] )
__global__ __launch_bounds__(256) void agg_kernel(
    const __half2* __restrict__ tin, float* __restrict__ tout,
    const float* __restrict__ b, int n)
{
    int warp = (blockIdx.x * blockDim.x + threadIdx.x) >> 5;
    int lane = threadIdx.x & 31;
    if (warp >= n) return;

    int s0 = g_row_start[warp];
    int s1 = g_row_start[warp + 1];

    float ax = 0.f, ay = 0.f;
    for (int e0 = s0; e0 < s1; e0 += 32) {
        int myE = e0 + lane;
        int mySrc = (myE < s1) ? g_csr_src[myE] : 0;
        int cnt = min(32, s1 - e0);
        for (int j = 0; j < cnt; j++) {
            int s = __shfl_sync(0xffffffffu, mySrc, j);
            float2 v = __half22float2(tin[(size_t)s * (HDIM / 2) + lane]);
            ax += v.x; ay += v.y;
        }
    }
    float nd = g_norm_dst[warp];
    float2 bb = *reinterpret_cast<const float2*>(b + lane * 2);
    float2 o;
    o.x = fmaxf(fmaf(ax, nd, bb.x), 0.f);
    o.y = fmaxf(fmaf(ay, nd, bb.y), 0.f);
    *reinterpret_cast<float2*>(tout + (size_t)warp * HDIM + lane * 2) = o;
}

// ---------------- score + loss: warp per node --------------------------------
__global__ __launch_bounds__(256) void score_kernel(
    const float* __restrict__ h, const float* __restrict__ labels,
    int label_off, int n)
{
    __shared__ float sw[8];
    int warpInBlock = threadIdx.x >> 5;
    int node = (blockIdx.x * blockDim.x + threadIdx.x) >> 5;
    int lane = threadIdx.x & 31;

    float term = 0.f;
    if (node < n) {
        float2 hv = *reinterpret_cast<const float2*>(h + (size_t)node * HDIM + lane * 2);
        float2 wv = *reinterpret_cast<const float2*>(&g_wv[lane * 2]);
        float p = hv.x * wv.x + hv.y * wv.y;
        #pragma unroll
        for (int o = 16; o; o >>= 1) p += __shfl_down_sync(0xffffffffu, p, o);
        if (lane == 0) {
            float sc = p + g_bsum;
            float y  = labels[label_off + node];
            term = fmaxf(sc, 0.f) + log1pf(expf(-fabsf(sc))) - sc * y;
        }
    }
    if (lane == 0) sw[warpInBlock] = term;
    __syncthreads();
    if (threadIdx.x == 0) {
        float s = 0.f;
        #pragma unroll
        for (int w = 0; w < 8; w++) s += sw[w];
        atomicAdd(&g_loss, (double)s);
    }
}

__global__ void finalize_kernel(float* __restrict__ out, double inv) {
    out[0] = (float)(g_loss * inv);
}

// ---------------- launch -----------------------------------------------------
extern "C" void kernel_launch(void* const* d_in, const int* in_sizes, int n_in,
                              void* d_out, int out_size) {
    const float* features = (const float*)d_in[0];
    const float* labels   = (const float*)d_in[1];
    const float* W1 = (const float*)d_in[2];
    const float* b1 = (const float*)d_in[3];
    const float* W2 = (const float*)d_in[4];
    const float* b2 = (const float*)d_in[5];
    const float* Wm = (const float*)d_in[6];
    const float* bm = (const float*)d_in[7];
    const int* src  = (const int*)d_in[8];
    const int* dst  = (const int*)d_in[9];
    const int* perm = (const int*)d_in[10];

    int E = in_sizes[8];
    int n = in_sizes[10];

    __half2* bufA; float* bufB; float* nsrc;
    cudaGetSymbolAddress((void**)&bufA, g_bufAh);
    cudaGetSymbolAddress((void**)&bufB, g_bufB);
    cudaGetSymbolAddress((void**)&nsrc, g_norm_src);

    const int SMEM128 = 128 * (128 + 4) * 4 + 128 * 68 * 4;  // 102,400 B
    const int SMEM64  = 128 * (64 + 4) * 4 + 64 * 68 * 4;    //  52,224 B
    static bool attr_set = false;
    // (idempotent, non-stream API; safe around graph capture)
    cudaFuncSetAttribute(gemm_kernel<128>, cudaFuncAttributeMaxDynamicSharedMemorySize, SMEM128);
    cudaFuncSetAttribute(gemm_kernel<64>,  cudaFuncAttributeMaxDynamicSharedMemorySize, SMEM64);
    (void)attr_set;

    int nb256  = (n + 255) / 256;
    int eb256  = (E + 255) / 256;
    int gemmB  = (n + 127) / 128;
    int warpB  = (n + 7) / 8;              // 8 warps (nodes) per 256-thread block
    int scanB  = (n + 1023) / 1024;

    zero_kernel<<<nb256, 256>>>(n, E);
    degree_kernel<<<eb256, 256>>>(src, dst, E);
    norm_kernel<<<nb256, 256>>>(n);
    scan1_kernel<<<scanB, 256>>>(n);
    scan2_kernel<<<scanB, 256>>>(n);
    scatter_kernel<<<eb256, 256>>>(src, dst, E);
    wv_kernel<<<1, 64>>>(Wm, bm);

    for (int enc = 0; enc < 2; enc++) {
        const int* p = enc ? perm : nullptr;
        gemm_kernel<128><<<gemmB, 256, SMEM128>>>(features, W1, p, nsrc, bufA, n);
        agg_kernel<<<warpB, 256>>>(bufA, bufB, b1, n);
        gemm_kernel<64><<<gemmB, 256, SMEM64>>>(bufB, W2, nullptr, nsrc, bufA, n);
        agg_kernel<<<warpB, 256>>>(bufA, bufB, b2, n);
        score_kernel<<<warpB, 256>>>(bufB, labels, enc * n, n);
    }

    finalize_kernel<<<1, 1>>>((float*)d_out, 0.5 / (double)n);
}

// round 4
// speedup vs baseline: 1.0880x; 1.0071x over previous
#include <cuda_runtime.h>
#include <cuda_fp16.h>
#include <math.h>
#include <stdint.h>

// Problem maxima (fixed by the dataset): N=100000, E=1600000, IN=128, H=64
#define MAXN 100000
#define MAXE 1600000
#define HDIM 64

typedef unsigned long long u64;

// ---------------- scratch (static device globals; no allocation) -------------
__device__ int     g_deg_in[MAXN];
__device__ int     g_deg_out[MAXN];
__device__ int     g_row_start[MAXN + 1];
__device__ int     g_cursor[MAXN];
__device__ int     g_csr_src[MAXE];
__device__ int     g_bsums[128];
__device__ float   g_norm_src[MAXN];
__device__ float   g_norm_dst[MAXN];
__device__ __half2 g_bufAh[(size_t)2 * MAXN * (HDIM / 2)]; // gemm out (fp16), both encoders
__device__ float   g_bufB[(size_t)2 * MAXN * HDIM];        // agg out (fp32), both encoders
__device__ float   g_wv[HDIM];
__device__ float   g_bsum;
__device__ double  g_loss;

// ---------------- f32x2 helpers (Blackwell packed FMA) ------------------------
__device__ __forceinline__ u64 pack2(float x) {
    u64 r; asm("mov.b64 %0, {%1, %1};" : "=l"(r) : "f"(x)); return r;
}
__device__ __forceinline__ void ffma2(u64& d, u64 a, u64 b) {
    asm("fma.rn.f32x2 %0, %1, %2, %0;" : "+l"(d) : "l"(a), "l"(b));
}
__device__ __forceinline__ float2 unpack2(u64 v) {
    float2 f; asm("mov.b64 {%0, %1}, %2;" : "=f"(f.x), "=f"(f.y) : "l"(v)); return f;
}

// ---------------- setup kernels ----------------------------------------------
__global__ void zero_kernel(int n, int E) {
    int i = blockIdx.x * blockDim.x + threadIdx.x;
    if (i < n) { g_deg_in[i] = 0; g_deg_out[i] = 0; g_cursor[i] = 0; }
    if (i == 0) { g_loss = 0.0; g_row_start[n] = E; }
}

__global__ void degree_kernel(const int* __restrict__ src,
                              const int* __restrict__ dst, int E) {
    int i = blockIdx.x * blockDim.x + threadIdx.x;
    if (i < E) {
        atomicAdd(&g_deg_out[src[i]], 1);
        atomicAdd(&g_deg_in[dst[i]], 1);
    }
}

__global__ void norm_kernel(int n) {
    int i = blockIdx.x * blockDim.x + threadIdx.x;
    if (i < n) {
        g_norm_src[i] = rsqrtf((float)max(g_deg_out[i], 1));
        g_norm_dst[i] = rsqrtf((float)max(g_deg_in[i], 1));
    }
}

// Phase 1: per-block (1024 elems) local exclusive scan + block total.
__global__ __launch_bounds__(256) void scan1_kernel(int n) {
    __shared__ int warp_tot[8];
    int b = blockIdx.x, t = threadIdx.x;
    int base = b * 1024 + t * 4;
    int d0 = (base + 0 < n) ? g_deg_in[base + 0] : 0;
    int d1 = (base + 1 < n) ? g_deg_in[base + 1] : 0;
    int d2 = (base + 2 < n) ? g_deg_in[base + 2] : 0;
    int d3 = (base + 3 < n) ? g_deg_in[base + 3] : 0;
    int tot = d0 + d1 + d2 + d3;

    int lane = t & 31, w = t >> 5;
    int inc = tot;
    #pragma unroll
    for (int off = 1; off < 32; off <<= 1) {
        int u = __shfl_up_sync(0xffffffffu, inc, off);
        if (lane >= off) inc += u;
    }
    if (lane == 31) warp_tot[w] = inc;
    __syncthreads();
    int woff = 0;
    #pragma unroll
    for (int i = 0; i < 8; i++) if (i < w) woff += warp_tot[i];
    int excl = woff + inc - tot;
    if (base + 0 < n) g_row_start[base + 0] = excl;
    if (base + 1 < n) g_row_start[base + 1] = excl + d0;
    if (base + 2 < n) g_row_start[base + 2] = excl + d0 + d1;
    if (base + 3 < n) g_row_start[base + 3] = excl + d0 + d1 + d2;
    if (t == 255) g_bsums[b] = woff + inc;   // block total
}

// Phase 2: each block adds the prefix of prior block totals (redundant loop).
__global__ __launch_bounds__(256) void scan2_kernel(int n) {
    int b = blockIdx.x, t = threadIdx.x;
    int off = 0;
    for (int i = 0; i < b; i++) off += g_bsums[i];
    int base = b * 1024 + t * 4;
    #pragma unroll
    for (int j = 0; j < 4; j++)
        if (base + j < n) g_row_start[base + j] += off;
}

__global__ void scatter_kernel(const int* __restrict__ src,
                               const int* __restrict__ dst, int E) {
    int i = blockIdx.x * blockDim.x + threadIdx.x;
    if (i < E) {
        int d = dst[i];
        int pos = atomicAdd(&g_cursor[d], 1);
        g_csr_src[g_row_start[d] + pos] = src[i];
    }
}

// wv[k] = sum_j Wm[k][j];  bsum = sum_j bm[j]
__global__ void wv_kernel(const float* __restrict__ Wm, const float* __restrict__ bm) {
    int k = threadIdx.x;
    if (k < HDIM) {
        float s = 0.f;
        #pragma unroll 8
        for (int j = 0; j < HDIM; j++) s += Wm[k * HDIM + j];
        g_wv[k] = s;
    }
    if (k == 0) {
        float b = 0.f;
        #pragma unroll 8
        for (int j = 0; j < HDIM; j++) b += bm[j];
        g_bsum = b;
    }
}

// ---------------- GEMM: out[n][j] = half( norm_src[n] * sum_k X[g(n)][k]*W[k][j] )
// gridDim.y = 2 (encoders). Tile 128 rows x 64 cols; thread tile 4x8; f32x2 FMA.
template <int K>
__global__ __launch_bounds__(256) void gemm_kernel(
    const float* __restrict__ X, const float* __restrict__ W,
    const int* __restrict__ perm, const float* __restrict__ nsrc,
    __half2* __restrict__ out, int n, size_t xStride, size_t outStride)
{
    extern __shared__ float smemf[];
    const int XS_STRIDE = K + 4;
    const int WS_STRIDE = 68;
    float* Xs = smemf;                    // [128][K+4]
    float* Ws = smemf + 128 * XS_STRIDE;  // [K][68]

    const int enc  = blockIdx.y;
    const float* Xb = X + (size_t)enc * xStride;
    out += (size_t)enc * outStride;

    const int tid  = threadIdx.x;
    const int row0 = blockIdx.x * 128;
    const int KV   = K / 4;

    const float4* X4 = reinterpret_cast<const float4*>(Xb);
    for (int v = tid; v < 128 * KV; v += 256) {
        int r  = v / KV;
        int kv = v - r * KV;
        int nd = row0 + r;
        float4 val = make_float4(0.f, 0.f, 0.f, 0.f);
        if (nd < n) {
            int g = (perm && enc) ? __ldg(&perm[nd]) : nd;
            val = __ldg(X4 + (size_t)g * KV + kv);
            float s = nsrc[nd];
            val.x *= s; val.y *= s; val.z *= s; val.w *= s;
        }
        *reinterpret_cast<float4*>(&Xs[r * XS_STRIDE + kv * 4]) = val;
    }
    const float4* W4 = reinterpret_cast<const float4*>(W);
    for (int v = tid; v < K * 16; v += 256) {
        int k  = v >> 4;
        int c4 = v & 15;
        *reinterpret_cast<float4*>(&Ws[k * WS_STRIDE + c4 * 4]) = __ldg(W4 + v);
    }
    __syncthreads();

    const int tcol = tid & 7;
    const int trow = tid >> 3;
    const int cg = tcol * 8;
    const int rg = trow * 4;

    u64 acc[4][4];
    #pragma unroll
    for (int r = 0; r < 4; r++)
        #pragma unroll
        for (int c = 0; c < 4; c++) acc[r][c] = 0ull;

    #pragma unroll 2
    for (int k0 = 0; k0 < K; k0 += 4) {
        float4 xr[4];
        #pragma unroll
        for (int r = 0; r < 4; r++)
            xr[r] = *reinterpret_cast<const float4*>(&Xs[(rg + r) * XS_STRIDE + k0]);
        #pragma unroll
        for (int kk = 0; kk < 4; kk++) {
            const float* wrow = &Ws[(k0 + kk) * WS_STRIDE + cg];
            ulonglong2 wA = *reinterpret_cast<const ulonglong2*>(wrow);
            ulonglong2 wB = *reinterpret_cast<const ulonglong2*>(wrow + 4);
            #pragma unroll
            for (int r = 0; r < 4; r++) {
                float xv = reinterpret_cast<const float*>(&xr[r])[kk];
                u64 xp = pack2(xv);
                ffma2(acc[r][0], xp, wA.x);
                ffma2(acc[r][1], xp, wA.y);
                ffma2(acc[r][2], xp, wB.x);
                ffma2(acc[r][3], xp, wB.y);
            }
        }
    }

    #pragma unroll
    for (int r = 0; r < 4; r++) {
        int nd = row0 + rg + r;
        if (nd < n) {
            __half2 hv[4];
            #pragma unroll
            for (int c = 0; c < 4; c++) {
                float2 f = unpack2(acc[r][c]);
                hv[c] = __floats2half2_rn(f.x, f.y);
            }
            *reinterpret_cast<uint4*>(&out[(size_t)nd * (HDIM / 2) + tcol * 4]) =
                *reinterpret_cast<const uint4*>(hv);
        }
    }
}

// ---------------- aggregation core: MLP-8 gather loop -------------------------
// Accumulates sum over in-edges of node into (ax, ay). Each lane owns 2 cols.
__device__ __forceinline__ void agg_gather(
    const __half2* __restrict__ tin, int node, int lane, float& ax, float& ay)
{
    int s0 = g_row_start[node];
    int s1 = g_row_start[node + 1];
    for (int e0 = s0; e0 < s1; e0 += 32) {
        int idx = e0 + lane;
        int mySrc = (idx < s1) ? g_csr_src[idx] : 0;   // 0 = safe dummy row
        int cnt = min(32, s1 - e0);
        for (int j0 = 0; j0 < cnt; j0 += 8) {
            float2 v[8];
            #pragma unroll
            for (int jj = 0; jj < 8; jj++) {
                int j = j0 + jj;
                int s = __shfl_sync(0xffffffffu, mySrc, j & 31);
                v[jj] = __half22float2(tin[(size_t)s * (HDIM / 2) + lane]);
                if (j >= cnt) { v[jj].x = 0.f; v[jj].y = 0.f; }
            }
            #pragma unroll
            for (int jj = 0; jj < 8; jj++) { ax += v[jj].x; ay += v[jj].y; }
        }
    }
}

// Layer-1 aggregation: writes fp32 features for the next GEMM. gridDim.y = 2.
__global__ __launch_bounds__(256) void agg_kernel(
    const __half2* __restrict__ tin, float* __restrict__ tout,
    const float* __restrict__ b, int n)
{
    int enc = blockIdx.y;
    tin  += (size_t)enc * n * (HDIM / 2);
    tout += (size_t)enc * n * HDIM;

    int node = (blockIdx.x * blockDim.x + threadIdx.x) >> 5;
    int lane = threadIdx.x & 31;
    if (node >= n) return;

    float ax = 0.f, ay = 0.f;
    agg_gather(tin, node, lane, ax, ay);

    float nd = g_norm_dst[node];
    float2 bb = *reinterpret_cast<const float2*>(b + lane * 2);
    float2 o;
    o.x = fmaxf(fmaf(ax, nd, bb.x), 0.f);
    o.y = fmaxf(fmaf(ay, nd, bb.y), 0.f);
    *reinterpret_cast<float2*>(tout + (size_t)node * HDIM + lane * 2) = o;
}

// Layer-2 aggregation fused with scoring + loss. gridDim.y = 2.
__global__ __launch_bounds__(256) void agg_score_kernel(
    const __half2* __restrict__ tin, const float* __restrict__ b,
    const float* __restrict__ labels, int n)
{
    __shared__ float sw[8];
    int enc = blockIdx.y;
    tin += (size_t)enc * n * (HDIM / 2);

    int node = (blockIdx.x * blockDim.x + threadIdx.x) >> 5;
    int lane = threadIdx.x & 31;
    int warpInBlock = threadIdx.x >> 5;

    float term = 0.f;
    if (node < n) {
        float ax = 0.f, ay = 0.f;
        agg_gather(tin, node, lane, ax, ay);

        float nd = g_norm_dst[node];
        float2 bb = *reinterpret_cast<const float2*>(b + lane * 2);
        float ox = fmaxf(fmaf(ax, nd, bb.x), 0.f);
        float oy = fmaxf(fmaf(ay, nd, bb.y), 0.f);

        float2 wv = *reinterpret_cast<const float2*>(&g_wv[lane * 2]);
        float p = ox * wv.x + oy * wv.y;
        #pragma unroll
        for (int o = 16; o; o >>= 1) p += __shfl_down_sync(0xffffffffu, p, o);
        if (lane == 0) {
            float sc = p + g_bsum;
            float y  = labels[(size_t)enc * n + node];
            term = fmaxf(sc, 0.f) + log1pf(expf(-fabsf(sc))) - sc * y;
        }
    }
    if (lane == 0) sw[warpInBlock] = term;
    __syncthreads();
    if (threadIdx.x == 0) {
        float s = 0.f;
        #pragma unroll
        for (int w = 0; w < 8; w++) s += sw[w];
        atomicAdd(&g_loss, (double)s);
    }
}

__global__ void finalize_kernel(float* __restrict__ out, double inv) {
    out[0] = (float)(g_loss * inv);
}

// ---------------- launch -----------------------------------------------------
extern "C" void kernel_launch(void* const* d_in, const int* in_sizes, int n_in,
                              void* d_out, int out_size) {
    const float* features = (const float*)d_in[0];
    const float* labels   = (const float*)d_in[1];
    const float* W1 = (const float*)d_in[2];
    const float* b1 = (const float*)d_in[3];
    const float* W2 = (const float*)d_in[4];
    const float* b2 = (const float*)d_in[5];
    const float* Wm = (const float*)d_in[6];
    const float* bm = (const float*)d_in[7];
    const int* src  = (const int*)d_in[8];
    const int* dst  = (const int*)d_in[9];
    const int* perm = (const int*)d_in[10];

    int E = in_sizes[8];
    int n = in_sizes[10];

    __half2* bufA; float* bufB; float* nsrc;
    cudaGetSymbolAddress((void**)&bufA, g_bufAh);
    cudaGetSymbolAddress((void**)&bufB, g_bufB);
    cudaGetSymbolAddress((void**)&nsrc, g_norm_src);

    const int SMEM128 = 128 * (128 + 4) * 4 + 128 * 68 * 4;  // 102,400 B
    const int SMEM64  = 128 * (64 + 4) * 4 + 64 * 68 * 4;    //  52,224 B
    cudaFuncSetAttribute(gemm_kernel<128>, cudaFuncAttributeMaxDynamicSharedMemorySize, SMEM128);
    cudaFuncSetAttribute(gemm_kernel<64>,  cudaFuncAttributeMaxDynamicSharedMemorySize, SMEM64);

    int nb256  = (n + 255) / 256;
    int eb256  = (E + 255) / 256;
    int scanB  = (n + 1023) / 1024;
    dim3 gemmG((n + 127) / 128, 2);
    dim3 warpG((n + 7) / 8, 2);          // warp per node, 2 encoders

    zero_kernel<<<nb256, 256>>>(n, E);
    degree_kernel<<<eb256, 256>>>(src, dst, E);
    norm_kernel<<<nb256, 256>>>(n);
    scan1_kernel<<<scanB, 256>>>(n);
    scan2_kernel<<<scanB, 256>>>(n);
    scatter_kernel<<<eb256, 256>>>(src, dst, E);
    wv_kernel<<<1, 64>>>(Wm, bm);

    // layer 1 (both encoders batched in gridDim.y)
    gemm_kernel<128><<<gemmG, 256, SMEM128>>>(features, W1, perm, nsrc, bufA,
                                              n, 0, (size_t)n * (HDIM / 2));
    agg_kernel<<<warpG, 256>>>(bufA, bufB, b1, n);
    // layer 2 + fused scoring/loss
    gemm_kernel<64><<<gemmG, 256, SMEM64>>>(bufB, W2, nullptr, nsrc, bufA,
                                            n, (size_t)n * HDIM, (size_t)n * (HDIM / 2));
    agg_score_kernel<<<warpG, 256>>>(bufA, b2, labels, n);

    finalize_kernel<<<1, 1>>>((float*)d_out, 0.5 / (double)n);
}

// round 5
// speedup vs baseline: 1.3383x; 1.2301x over previous
#include <cuda_runtime.h>
#include <cuda_fp16.h>
#include <math.h>
#include <stdint.h>

// Problem maxima (fixed by the dataset): N=100000, E=1600000, IN=128, H=64
#define MAXN 100000
#define MAXE 1600000
#define HDIM 64

typedef unsigned long long u64;

// ---------------- scratch (static device globals; no allocation) -------------
__device__ int     g_deg_in[MAXN];
__device__ int     g_deg_out[MAXN];
__device__ int     g_row_start[MAXN + 1];
__device__ int     g_cursor[MAXN];
__device__ int     g_csr_src[MAXE];
__device__ int     g_bsums[128];
__device__ float   g_norm_src[MAXN];
__device__ float   g_norm_dst[MAXN];
// Encoder-interleaved: row (node*2 + enc)
__device__ __half2 g_bufAh[(size_t)2 * MAXN * (HDIM / 2)]; // gemm out (fp16), agg in
__device__ float   g_bufB[(size_t)2 * MAXN * HDIM];        // agg out (fp32), gemm in
__device__ float   g_wv[HDIM];
__device__ float   g_bsum;
__device__ double  g_loss;

// ---------------- f32x2 helpers (Blackwell packed FMA) ------------------------
__device__ __forceinline__ u64 pack2(float x) {
    u64 r; asm("mov.b64 %0, {%1, %1};" : "=l"(r) : "f"(x)); return r;
}
__device__ __forceinline__ void ffma2(u64& d, u64 a, u64 b) {
    asm("fma.rn.f32x2 %0, %1, %2, %0;" : "+l"(d) : "l"(a), "l"(b));
}
__device__ __forceinline__ float2 unpack2(u64 v) {
    float2 f; asm("mov.b64 {%0, %1}, %2;" : "=f"(f.x), "=f"(f.y) : "l"(v)); return f;
}

// ---------------- setup kernels ----------------------------------------------
__global__ void zero_kernel(int n, int E) {
    int i = blockIdx.x * blockDim.x + threadIdx.x;
    if (i < n) { g_deg_in[i] = 0; g_deg_out[i] = 0; g_cursor[i] = 0; }
    if (i == 0) { g_loss = 0.0; g_row_start[n] = E; }
}

__global__ void degree_kernel(const int* __restrict__ src,
                              const int* __restrict__ dst, int E) {
    int i = blockIdx.x * blockDim.x + threadIdx.x;
    if (i < E) {
        atomicAdd(&g_deg_out[src[i]], 1);
        atomicAdd(&g_deg_in[dst[i]], 1);
    }
}

__global__ void norm_kernel(int n) {
    int i = blockIdx.x * blockDim.x + threadIdx.x;
    if (i < n) {
        g_norm_src[i] = rsqrtf((float)max(g_deg_out[i], 1));
        g_norm_dst[i] = rsqrtf((float)max(g_deg_in[i], 1));
    }
}

// Phase 1: per-block (1024 elems) local exclusive scan + block total.
__global__ __launch_bounds__(256) void scan1_kernel(int n) {
    __shared__ int warp_tot[8];
    int b = blockIdx.x, t = threadIdx.x;
    int base = b * 1024 + t * 4;
    int d0 = (base + 0 < n) ? g_deg_in[base + 0] : 0;
    int d1 = (base + 1 < n) ? g_deg_in[base + 1] : 0;
    int d2 = (base + 2 < n) ? g_deg_in[base + 2] : 0;
    int d3 = (base + 3 < n) ? g_deg_in[base + 3] : 0;
    int tot = d0 + d1 + d2 + d3;

    int lane = t & 31, w = t >> 5;
    int inc = tot;
    #pragma unroll
    for (int off = 1; off < 32; off <<= 1) {
        int u = __shfl_up_sync(0xffffffffu, inc, off);
        if (lane >= off) inc += u;
    }
    if (lane == 31) warp_tot[w] = inc;
    __syncthreads();
    int woff = 0;
    #pragma unroll
    for (int i = 0; i < 8; i++) if (i < w) woff += warp_tot[i];
    int excl = woff + inc - tot;
    if (base + 0 < n) g_row_start[base + 0] = excl;
    if (base + 1 < n) g_row_start[base + 1] = excl + d0;
    if (base + 2 < n) g_row_start[base + 2] = excl + d0 + d1;
    if (base + 3 < n) g_row_start[base + 3] = excl + d0 + d1 + d2;
    if (t == 255) g_bsums[b] = woff + inc;
}

// Phase 2: each block adds the prefix of prior block totals (redundant loop).
__global__ __launch_bounds__(256) void scan2_kernel(int n) {
    int b = blockIdx.x, t = threadIdx.x;
    int off = 0;
    for (int i = 0; i < b; i++) off += g_bsums[i];
    int base = b * 1024 + t * 4;
    #pragma unroll
    for (int j = 0; j < 4; j++)
        if (base + j < n) g_row_start[base + j] += off;
}

__global__ void scatter_kernel(const int* __restrict__ src,
                               const int* __restrict__ dst, int E) {
    int i = blockIdx.x * blockDim.x + threadIdx.x;
    if (i < E) {
        int d = dst[i];
        int pos = atomicAdd(&g_cursor[d], 1);
        g_csr_src[g_row_start[d] + pos] = src[i];
    }
}

// wv[k] = sum_j Wm[k][j];  bsum = sum_j bm[j]
__global__ void wv_kernel(const float* __restrict__ Wm, const float* __restrict__ bm) {
    int k = threadIdx.x;
    if (k < HDIM) {
        float s = 0.f;
        #pragma unroll 8
        for (int j = 0; j < HDIM; j++) s += Wm[k * HDIM + j];
        g_wv[k] = s;
    }
    if (k == 0) {
        float b = 0.f;
        #pragma unroll 8
        for (int j = 0; j < HDIM; j++) b += bm[j];
        g_bsum = b;
    }
}

// ---------------- GEMM layer 1: out[(n*2+enc)][j] (fp16) ----------------------
// gridDim.y = 2 (encoders). Tile 128 rows x 64 cols; thread tile 4x8; f32x2 FMA.
__global__ __launch_bounds__(256) void gemm1_kernel(
    const float* __restrict__ X, const float* __restrict__ W,
    const int* __restrict__ perm, const float* __restrict__ nsrc,
    __half2* __restrict__ out, int n)
{
    const int K = 128;
    extern __shared__ float smemf[];
    const int XS_STRIDE = K + 4;
    const int WS_STRIDE = 68;
    float* Xs = smemf;
    float* Ws = smemf + 128 * XS_STRIDE;

    const int enc  = blockIdx.y;
    const int tid  = threadIdx.x;
    const int row0 = blockIdx.x * 128;
    const int KV   = K / 4;

    const float4* X4 = reinterpret_cast<const float4*>(X);
    for (int v = tid; v < 128 * KV; v += 256) {
        int r  = v / KV;
        int kv = v - r * KV;
        int nd = row0 + r;
        float4 val = make_float4(0.f, 0.f, 0.f, 0.f);
        if (nd < n) {
            int g = enc ? __ldg(&perm[nd]) : nd;
            val = __ldg(X4 + (size_t)g * KV + kv);
            float s = nsrc[nd];
            val.x *= s; val.y *= s; val.z *= s; val.w *= s;
        }
        *reinterpret_cast<float4*>(&Xs[r * XS_STRIDE + kv * 4]) = val;
    }
    const float4* W4 = reinterpret_cast<const float4*>(W);
    for (int v = tid; v < K * 16; v += 256) {
        *reinterpret_cast<float4*>(&Ws[(v >> 4) * WS_STRIDE + (v & 15) * 4]) = __ldg(W4 + v);
    }
    __syncthreads();

    const int tcol = tid & 7;
    const int trow = tid >> 3;
    const int cg = tcol * 8;
    const int rg = trow * 4;

    u64 acc[4][4];
    #pragma unroll
    for (int r = 0; r < 4; r++)
        #pragma unroll
        for (int c = 0; c < 4; c++) acc[r][c] = 0ull;

    #pragma unroll 2
    for (int k0 = 0; k0 < K; k0 += 4) {
        float4 xr[4];
        #pragma unroll
        for (int r = 0; r < 4; r++)
            xr[r] = *reinterpret_cast<const float4*>(&Xs[(rg + r) * XS_STRIDE + k0]);
        #pragma unroll
        for (int kk = 0; kk < 4; kk++) {
            const float* wrow = &Ws[(k0 + kk) * WS_STRIDE + cg];
            ulonglong2 wA = *reinterpret_cast<const ulonglong2*>(wrow);
            ulonglong2 wB = *reinterpret_cast<const ulonglong2*>(wrow + 4);
            #pragma unroll
            for (int r = 0; r < 4; r++) {
                float xv = reinterpret_cast<const float*>(&xr[r])[kk];
                u64 xp = pack2(xv);
                ffma2(acc[r][0], xp, wA.x);
                ffma2(acc[r][1], xp, wA.y);
                ffma2(acc[r][2], xp, wB.x);
                ffma2(acc[r][3], xp, wB.y);
            }
        }
    }

    #pragma unroll
    for (int r = 0; r < 4; r++) {
        int nd = row0 + rg + r;
        if (nd < n) {
            __half2 hv[4];
            #pragma unroll
            for (int c = 0; c < 4; c++) {
                float2 f = unpack2(acc[r][c]);
                hv[c] = __floats2half2_rn(f.x, f.y);
            }
            *reinterpret_cast<uint4*>(&out[((size_t)nd * 2 + enc) * (HDIM / 2) + tcol * 4]) =
                *reinterpret_cast<const uint4*>(hv);
        }
    }
}

// ---------------- GEMM layer 2: rows are already encoder-interleaved ----------
// nRows = 2*n; norm index = row >> 1. K = 64.
__global__ __launch_bounds__(256) void gemm2_kernel(
    const float* __restrict__ X, const float* __restrict__ W,
    const float* __restrict__ nsrc, __half2* __restrict__ out, int nRows)
{
    const int K = 64;
    extern __shared__ float smemf[];
    const int XS_STRIDE = K + 4;
    const int WS_STRIDE = 68;
    float* Xs = smemf;
    float* Ws = smemf + 128 * XS_STRIDE;

    const int tid  = threadIdx.x;
    const int row0 = blockIdx.x * 128;
    const int KV   = K / 4;

    const float4* X4 = reinterpret_cast<const float4*>(X);
    for (int v = tid; v < 128 * KV; v += 256) {
        int r  = v / KV;
        int kv = v - r * KV;
        int nd = row0 + r;
        float4 val = make_float4(0.f, 0.f, 0.f, 0.f);
        if (nd < nRows) {
            val = __ldg(X4 + (size_t)nd * KV + kv);
            float s = nsrc[nd >> 1];
            val.x *= s; val.y *= s; val.z *= s; val.w *= s;
        }
        *reinterpret_cast<float4*>(&Xs[r * XS_STRIDE + kv * 4]) = val;
    }
    const float4* W4 = reinterpret_cast<const float4*>(W);
    for (int v = tid; v < K * 16; v += 256) {
        *reinterpret_cast<float4*>(&Ws[(v >> 4) * WS_STRIDE + (v & 15) * 4]) = __ldg(W4 + v);
    }
    __syncthreads();

    const int tcol = tid & 7;
    const int trow = tid >> 3;
    const int cg = tcol * 8;
    const int rg = trow * 4;

    u64 acc[4][4];
    #pragma unroll
    for (int r = 0; r < 4; r++)
        #pragma unroll
        for (int c = 0; c < 4; c++) acc[r][c] = 0ull;

    #pragma unroll 2
    for (int k0 = 0; k0 < K; k0 += 4) {
        float4 xr[4];
        #pragma unroll
        for (int r = 0; r < 4; r++)
            xr[r] = *reinterpret_cast<const float4*>(&Xs[(rg + r) * XS_STRIDE + k0]);
        #pragma unroll
        for (int kk = 0; kk < 4; kk++) {
            const float* wrow = &Ws[(k0 + kk) * WS_STRIDE + cg];
            ulonglong2 wA = *reinterpret_cast<const ulonglong2*>(wrow);
            ulonglong2 wB = *reinterpret_cast<const ulonglong2*>(wrow + 4);
            #pragma unroll
            for (int r = 0; r < 4; r++) {
                float xv = reinterpret_cast<const float*>(&xr[r])[kk];
                u64 xp = pack2(xv);
                ffma2(acc[r][0], xp, wA.x);
                ffma2(acc[r][1], xp, wA.y);
                ffma2(acc[r][2], xp, wB.x);
                ffma2(acc[r][3], xp, wB.y);
            }
        }
    }

    #pragma unroll
    for (int r = 0; r < 4; r++) {
        int nd = row0 + rg + r;
        if (nd < nRows) {
            __half2 hv[4];
            #pragma unroll
            for (int c = 0; c < 4; c++) {
                float2 f = unpack2(acc[r][c]);
                hv[c] = __floats2half2_rn(f.x, f.y);
            }
            *reinterpret_cast<uint4*>(&out[(size_t)nd * (HDIM / 2) + tcol * 4]) =
                *reinterpret_cast<const uint4*>(hv);
        }
    }
}

// ---------------- aggregation core: smem-staged indices, batched LDGs ---------
// One warp aggregates BOTH encoders of one node. srcs = smem slice [32] for
// this warp. Accumulates enc0 into (a0x,a0y), enc1 into (a1x,a1y).
__device__ __forceinline__ void agg_gather2(
    const __half2* __restrict__ tin, int* __restrict__ srcs,
    int node, int lane,
    float& a0x, float& a0y, float& a1x, float& a1y)
{
    int s0 = __ldg(&g_row_start[node]);
    int s1 = __ldg(&g_row_start[node + 1]);
    for (int base = s0; base < s1; base += 32) {
        int idx = base + lane;
        srcs[lane] = (idx < s1) ? __ldg(&g_csr_src[idx]) : 0;  // 0 = safe dummy
        __syncwarp();
        int cnt = min(32, s1 - base);
        for (int j0 = 0; j0 < cnt; j0 += 8) {
            float2 v0[8], v1[8];
            #pragma unroll
            for (int jj = 0; jj < 8; jj++) {
                int s = srcs[j0 + jj];                 // uniform smem read
                const __half2* p = tin + ((size_t)s * 2) * (HDIM / 2) + lane;
                v0[jj] = __half22float2(__ldg(p));
                v1[jj] = __half22float2(__ldg(p + (HDIM / 2)));
            }
            #pragma unroll
            for (int jj = 0; jj < 8; jj++) {
                if (j0 + jj < cnt) {
                    a0x += v0[jj].x; a0y += v0[jj].y;
                    a1x += v1[jj].x; a1y += v1[jj].y;
                }
            }
        }
        __syncwarp();
    }
}

// Layer-1 aggregation: writes interleaved fp32 rows for gemm2.
__global__ __launch_bounds__(256) void agg_kernel(
    const __half2* __restrict__ tin, float* __restrict__ tout,
    const float* __restrict__ b, int n)
{
    __shared__ int smem_srcs[8][32];
    int node = (blockIdx.x * blockDim.x + threadIdx.x) >> 5;
    int lane = threadIdx.x & 31;
    int wib  = threadIdx.x >> 5;
    if (node >= n) return;

    float a0x = 0.f, a0y = 0.f, a1x = 0.f, a1y = 0.f;
    agg_gather2(tin, smem_srcs[wib], node, lane, a0x, a0y, a1x, a1y);

    float nd = g_norm_dst[node];
    float2 bb = *reinterpret_cast<const float2*>(b + lane * 2);
    float2 o0, o1;
    o0.x = fmaxf(fmaf(a0x, nd, bb.x), 0.f);
    o0.y = fmaxf(fmaf(a0y, nd, bb.y), 0.f);
    o1.x = fmaxf(fmaf(a1x, nd, bb.x), 0.f);
    o1.y = fmaxf(fmaf(a1y, nd, bb.y), 0.f);
    float* r0 = tout + ((size_t)node * 2) * HDIM;
    *reinterpret_cast<float2*>(r0 + lane * 2) = o0;
    *reinterpret_cast<float2*>(r0 + HDIM + lane * 2) = o1;
}

// Layer-2 aggregation fused with scoring + loss (both encoders per warp).
__global__ __launch_bounds__(256) void agg_score_kernel(
    const __half2* __restrict__ tin, const float* __restrict__ b,
    const float* __restrict__ labels, int n)
{
    __shared__ int smem_srcs[8][32];
    __shared__ float sw[8];
    int node = (blockIdx.x * blockDim.x + threadIdx.x) >> 5;
    int lane = threadIdx.x & 31;
    int wib  = threadIdx.x >> 5;

    float term = 0.f;
    if (node < n) {
        float a0x = 0.f, a0y = 0.f, a1x = 0.f, a1y = 0.f;
        agg_gather2(tin, smem_srcs[wib], node, lane, a0x, a0y, a1x, a1y);

        float nd = g_norm_dst[node];
        float2 bb = *reinterpret_cast<const float2*>(b + lane * 2);
        float2 wv = *reinterpret_cast<const float2*>(&g_wv[lane * 2]);

        float o0x = fmaxf(fmaf(a0x, nd, bb.x), 0.f);
        float o0y = fmaxf(fmaf(a0y, nd, bb.y), 0.f);
        float o1x = fmaxf(fmaf(a1x, nd, bb.x), 0.f);
        float o1y = fmaxf(fmaf(a1y, nd, bb.y), 0.f);

        float p0 = o0x * wv.x + o0y * wv.y;
        float p1 = o1x * wv.x + o1y * wv.y;
        #pragma unroll
        for (int o = 16; o; o >>= 1) {
            p0 += __shfl_down_sync(0xffffffffu, p0, o);
            p1 += __shfl_down_sync(0xffffffffu, p1, o);
        }
        if (lane == 0) {
            float sc0 = p0 + g_bsum;
            float sc1 = p1 + g_bsum;
            float y0 = labels[node];
            float y1 = labels[(size_t)n + node];
            term = fmaxf(sc0, 0.f) + log1pf(expf(-fabsf(sc0))) - sc0 * y0
                 + fmaxf(sc1, 0.f) + log1pf(expf(-fabsf(sc1))) - sc1 * y1;
        }
    }
    if (lane == 0) sw[wib] = term;
    __syncthreads();
    if (threadIdx.x == 0) {
        float s = 0.f;
        #pragma unroll
        for (int w = 0; w < 8; w++) s += sw[w];
        atomicAdd(&g_loss, (double)s);
    }
}

__global__ void finalize_kernel(float* __restrict__ out, double inv) {
    out[0] = (float)(g_loss * inv);
}

// ---------------- launch -----------------------------------------------------
extern "C" void kernel_launch(void* const* d_in, const int* in_sizes, int n_in,
                              void* d_out, int out_size) {
    const float* features = (const float*)d_in[0];
    const float* labels   = (const float*)d_in[1];
    const float* W1 = (const float*)d_in[2];
    const float* b1 = (const float*)d_in[3];
    const float* W2 = (const float*)d_in[4];
    const float* b2 = (const float*)d_in[5];
    const float* Wm = (const float*)d_in[6];
    const float* bm = (const float*)d_in[7];
    const int* src  = (const int*)d_in[8];
    const int* dst  = (const int*)d_in[9];
    const int* perm = (const int*)d_in[10];

    int E = in_sizes[8];
    int n = in_sizes[10];

    __half2* bufA; float* bufB; float* nsrc;
    cudaGetSymbolAddress((void**)&bufA, g_bufAh);
    cudaGetSymbolAddress((void**)&bufB, g_bufB);
    cudaGetSymbolAddress((void**)&nsrc, g_norm_src);

    const int SMEM1 = 128 * (128 + 4) * 4 + 128 * 68 * 4;  // 102,400 B
    const int SMEM2 = 128 * (64 + 4) * 4 + 64 * 68 * 4;    //  52,224 B
    cudaFuncSetAttribute(gemm1_kernel, cudaFuncAttributeMaxDynamicSharedMemorySize, SMEM1);
    cudaFuncSetAttribute(gemm2_kernel, cudaFuncAttributeMaxDynamicSharedMemorySize, SMEM2);

    int nb256  = (n + 255) / 256;
    int eb256  = (E + 255) / 256;
    int scanB  = (n + 1023) / 1024;
    dim3 gemm1G((n + 127) / 128, 2);
    int  gemm2B = (2 * n + 127) / 128;
    int  warpB  = (n + 7) / 8;           // warp per node (both encoders)

    // NOTE: gemm1 placed 4th so the fixed-slot ncu capture profiles it.
    zero_kernel<<<nb256, 256>>>(n, E);
    degree_kernel<<<eb256, 256>>>(src, dst, E);
    norm_kernel<<<nb256, 256>>>(n);
    gemm1_kernel<<<gemm1G, 256, SMEM1>>>(features, W1, perm, nsrc, bufA, n);
    scan1_kernel<<<scanB, 256>>>(n);
    scan2_kernel<<<scanB, 256>>>(n);
    scatter_kernel<<<eb256, 256>>>(src, dst, E);
    wv_kernel<<<1, 64>>>(Wm, bm);

    agg_kernel<<<warpB, 256>>>(bufA, bufB, b1, n);
    gemm2_kernel<<<gemm2B, 256, SMEM2>>>(bufB, W2, nsrc, bufA, 2 * n);
    agg_score_kernel<<<warpB, 256>>>(bufA, b2, labels, n);

    finalize_kernel<<<1, 1>>>((float*)d_out, 0.5 / (double)n);
}

// round 9
// speedup vs baseline: 1.7025x; 1.2722x over previous
#include <cuda_runtime.h>
#include <cuda_fp16.h>
#include <cuda_bf16.h>
#include <math.h>
#include <stdint.h>
#include <string.h>

// Problem maxima: N=100000, E=1600000, IN=128, H=64
#define MAXN 100000
#define MAXE 1600000
#define HDIM 64

typedef unsigned long long u64;

// ---------------- scratch (static device globals) ----------------------------
__device__ int     g_deg_in[MAXN];
__device__ int     g_deg_out[MAXN];
__device__ int     g_row_start[MAXN + 1];
__device__ int     g_cursor[MAXN];
__device__ int     g_csr_src[MAXE];
__device__ int     g_bsums[128];
__device__ float   g_norm_src[MAXN];
__device__ float   g_norm_dst[MAXN];
// Encoder-interleaved: row (node*2 + enc)
__device__ __half2 g_bufAh[(size_t)2 * MAXN * (HDIM / 2)];       // gemm out (fp16), agg in
__device__ __align__(16) __nv_bfloat16 g_bufBh[(size_t)2 * MAXN * HDIM]; // agg out (bf16, nsrc-folded)
__device__ float   g_wv[HDIM];
__device__ float   g_bsum;
__device__ double  g_loss;

// ---------------- f32x2 helpers (Blackwell packed FMA) ------------------------
__device__ __forceinline__ u64 pack2(float x) {
    u64 r; asm("mov.b64 %0, {%1, %1};" : "=l"(r) : "f"(x)); return r;
}
__device__ __forceinline__ void ffma2(u64& d, u64 a, u64 b) {
    asm("fma.rn.f32x2 %0, %1, %2, %0;" : "+l"(d) : "l"(a), "l"(b));
}
__device__ __forceinline__ float2 unpack2(u64 v) {
    float2 f; asm("mov.b64 {%0, %1}, %2;" : "=f"(f.x), "=f"(f.y) : "l"(v)); return f;
}
__device__ __forceinline__ uint32_t bf2_bits(__nv_bfloat162 v) {
    uint32_t r; memcpy(&r, &v, 4); return r;
}

// ---------------- setup kernels ----------------------------------------------
__global__ void zero_kernel(int n, int E) {
    int i = blockIdx.x * blockDim.x + threadIdx.x;
    if (i < n) { g_deg_in[i] = 0; g_deg_out[i] = 0; g_cursor[i] = 0; }
    if (i == 0) { g_loss = 0.0; g_row_start[n] = E; }
}

__global__ void degree_kernel(const int* __restrict__ src,
                              const int* __restrict__ dst, int E) {
    int i = blockIdx.x * blockDim.x + threadIdx.x;
    if (i < E) {
        atomicAdd(&g_deg_out[src[i]], 1);
        atomicAdd(&g_deg_in[dst[i]], 1);
    }
}

__global__ void norm_kernel(int n) {
    int i = blockIdx.x * blockDim.x + threadIdx.x;
    if (i < n) {
        g_norm_src[i] = rsqrtf((float)max(g_deg_out[i], 1));
        g_norm_dst[i] = rsqrtf((float)max(g_deg_in[i], 1));
    }
}

__global__ __launch_bounds__(256) void scan1_kernel(int n) {
    __shared__ int warp_tot[8];
    int b = blockIdx.x, t = threadIdx.x;
    int base = b * 1024 + t * 4;
    int d0 = (base + 0 < n) ? g_deg_in[base + 0] : 0;
    int d1 = (base + 1 < n) ? g_deg_in[base + 1] : 0;
    int d2 = (base + 2 < n) ? g_deg_in[base + 2] : 0;
    int d3 = (base + 3 < n) ? g_deg_in[base + 3] : 0;
    int tot = d0 + d1 + d2 + d3;
    int lane = t & 31, w = t >> 5;
    int inc = tot;
    #pragma unroll
    for (int off = 1; off < 32; off <<= 1) {
        int u = __shfl_up_sync(0xffffffffu, inc, off);
        if (lane >= off) inc += u;
    }
    if (lane == 31) warp_tot[w] = inc;
    __syncthreads();
    int woff = 0;
    #pragma unroll
    for (int i = 0; i < 8; i++) if (i < w) woff += warp_tot[i];
    int excl = woff + inc - tot;
    if (base + 0 < n) g_row_start[base + 0] = excl;
    if (base + 1 < n) g_row_start[base + 1] = excl + d0;
    if (base + 2 < n) g_row_start[base + 2] = excl + d0 + d1;
    if (base + 3 < n) g_row_start[base + 3] = excl + d0 + d1 + d2;
    if (t == 255) g_bsums[b] = woff + inc;
}

__global__ __launch_bounds__(256) void scan2_kernel(int n) {
    int b = blockIdx.x, t = threadIdx.x;
    int off = 0;
    for (int i = 0; i < b; i++) off += g_bsums[i];
    int base = b * 1024 + t * 4;
    #pragma unroll
    for (int j = 0; j < 4; j++)
        if (base + j < n) g_row_start[base + j] += off;
}

__global__ void scatter_kernel(const int* __restrict__ src,
                               const int* __restrict__ dst, int E) {
    int i = blockIdx.x * blockDim.x + threadIdx.x;
    if (i < E) {
        int d = dst[i];
        int pos = atomicAdd(&g_cursor[d], 1);
        g_csr_src[g_row_start[d] + pos] = src[i];
    }
}

__global__ void wv_kernel(const float* __restrict__ Wm, const float* __restrict__ bm) {
    int k = threadIdx.x;
    if (k < HDIM) {
        float s = 0.f;
        #pragma unroll 8
        for (int j = 0; j < HDIM; j++) s += Wm[k * HDIM + j];
        g_wv[k] = s;
    }
    if (k == 0) {
        float b = 0.f;
        #pragma unroll 8
        for (int j = 0; j < HDIM; j++) b += bm[j];
        g_bsum = b;
    }
}

// ---------------- GEMM layer 1: fp32 X -> bf16 smem; out fp16 interleaved -----
// CTA tile 256 rows x 64 cols, K=128. 256 threads, thread tile 8x8, f32x2 FMA.
// gridDim.y = 2 (encoders). out row index = node*2 + enc.
__global__ __launch_bounds__(256, 2) void gemm1_kernel(
    const float* __restrict__ X, const float* __restrict__ W,
    const int* __restrict__ perm, const float* __restrict__ nsrc,
    __half2* __restrict__ out, int n)
{
    const int K = 128;
    const int XS_STRIDE = K + 8;   // bf16 units
    const int WS_STRIDE = 68;      // fp32 units
    extern __shared__ char smemc[];
    __nv_bfloat16* Xs = reinterpret_cast<__nv_bfloat16*>(smemc);           // 256 x 136 bf16
    float* Ws = reinterpret_cast<float*>(smemc + 256 * XS_STRIDE * 2);     // 128 x 68 fp32

    const int tid  = threadIdx.x;
    const int enc  = blockIdx.y;
    const int row0 = blockIdx.x * 256;

    // stage X: fuse perm-gather + nsrc scale + bf16 convert
    const float4* X4 = reinterpret_cast<const float4*>(X);
    for (int v = tid; v < 256 * 32; v += 256) {
        int r = v >> 5, kv = v & 31;
        int nd = row0 + r;
        float4 val = make_float4(0.f, 0.f, 0.f, 0.f);
        if (nd < n) {
            int g = enc ? __ldg(&perm[nd]) : nd;
            val = __ldg(X4 + (size_t)g * 32 + kv);
            float s = nsrc[nd];
            val.x *= s; val.y *= s; val.z *= s; val.w *= s;
        }
        u64 pk = ((u64)bf2_bits(__floats2bfloat162_rn(val.z, val.w)) << 32)
               | bf2_bits(__floats2bfloat162_rn(val.x, val.y));
        *reinterpret_cast<u64*>(&Xs[r * XS_STRIDE + kv * 4]) = pk;
    }
    const float4* W4 = reinterpret_cast<const float4*>(W);
    for (int v = tid; v < K * 16; v += 256) {
        *reinterpret_cast<float4*>(&Ws[(v >> 4) * WS_STRIDE + (v & 15) * 4]) = __ldg(W4 + v);
    }
    __syncthreads();

    const int tcol = tid & 7;
    const int trow = tid >> 3;
    const int cg = tcol * 8;
    const int rg = trow * 8;

    u64 acc[8][4];
    #pragma unroll
    for (int r = 0; r < 8; r++)
        #pragma unroll
        for (int c = 0; c < 4; c++) acc[r][c] = 0ull;

    #pragma unroll 2
    for (int k0 = 0; k0 < K; k0 += 4) {
        uint2 xb[8];
        #pragma unroll
        for (int r = 0; r < 8; r++)
            xb[r] = *reinterpret_cast<const uint2*>(&Xs[(rg + r) * XS_STRIDE + k0]);
        #pragma unroll
        for (int kk = 0; kk < 4; kk++) {
            const float* wrow = &Ws[(k0 + kk) * WS_STRIDE + cg];
            ulonglong2 wA = *reinterpret_cast<const ulonglong2*>(wrow);
            ulonglong2 wB = *reinterpret_cast<const ulonglong2*>(wrow + 4);
            #pragma unroll
            for (int r = 0; r < 8; r++) {
                uint32_t b = (kk < 2) ? xb[r].x : xb[r].y;
                uint32_t xbits = (kk & 1) ? (b & 0xFFFF0000u) : (b << 16);
                u64 xp = pack2(__uint_as_float(xbits));
                ffma2(acc[r][0], xp, wA.x);
                ffma2(acc[r][1], xp, wA.y);
                ffma2(acc[r][2], xp, wB.x);
                ffma2(acc[r][3], xp, wB.y);
            }
        }
    }

    #pragma unroll
    for (int r = 0; r < 8; r++) {
        int nd = row0 + rg + r;
        if (nd < n) {
            __half2 hv[4];
            #pragma unroll
            for (int c = 0; c < 4; c++) {
                float2 f = unpack2(acc[r][c]);
                hv[c] = __floats2half2_rn(f.x, f.y);
            }
            *reinterpret_cast<uint4*>(&out[((size_t)nd * 2 + enc) * (HDIM / 2) + tcol * 4]) =
                *reinterpret_cast<const uint4*>(hv);
        }
    }
}

// ---------------- GEMM layer 2: bf16 X (pre-scaled) -> fp16 out ---------------
// CTA tile 256 rows x 64 cols, K=64. Rows are 2n encoder-interleaved.
__global__ __launch_bounds__(256, 2) void gemm2_kernel(
    const __nv_bfloat16* __restrict__ X, const float* __restrict__ W,
    __half2* __restrict__ out, int nRows)
{
    const int K = 64;
    const int XS_STRIDE = K + 8;   // 72 bf16
    const int WS_STRIDE = 68;
    extern __shared__ char smemc[];
    __nv_bfloat16* Xs = reinterpret_cast<__nv_bfloat16*>(smemc);           // 256 x 72 bf16
    float* Ws = reinterpret_cast<float*>(smemc + 256 * XS_STRIDE * 2);     // 64 x 68 fp32

    const int tid  = threadIdx.x;
    const int row0 = blockIdx.x * 256;

    // stage X: straight 16B copies (already bf16 + pre-scaled)
    const uint4* Xg = reinterpret_cast<const uint4*>(X);
    for (int v = tid; v < 256 * 8; v += 256) {
        int r = v >> 3, q = v & 7;
        int nd = row0 + r;
        uint4 val = make_uint4(0u, 0u, 0u, 0u);
        if (nd < nRows) val = __ldg(Xg + (size_t)nd * 8 + q);
        *reinterpret_cast<uint4*>(&Xs[r * XS_STRIDE + q * 8]) = val;
    }
    const float4* W4 = reinterpret_cast<const float4*>(W);
    for (int v = tid; v < K * 16; v += 256) {
        *reinterpret_cast<float4*>(&Ws[(v >> 4) * WS_STRIDE + (v & 15) * 4]) = __ldg(W4 + v);
    }
    __syncthreads();

    const int tcol = tid & 7;
    const int trow = tid >> 3;
    const int cg = tcol * 8;
    const int rg = trow * 8;

    u64 acc[8][4];
    #pragma unroll
    for (int r = 0; r < 8; r++)
        #pragma unroll
        for (int c = 0; c < 4; c++) acc[r][c] = 0ull;

    #pragma unroll 2
    for (int k0 = 0; k0 < K; k0 += 4) {
        uint2 xb[8];
        #pragma unroll
        for (int r = 0; r < 8; r++)
            xb[r] = *reinterpret_cast<const uint2*>(&Xs[(rg + r) * XS_STRIDE + k0]);
        #pragma unroll
        for (int kk = 0; kk < 4; kk++) {
            const float* wrow = &Ws[(k0 + kk) * WS_STRIDE + cg];
            ulonglong2 wA = *reinterpret_cast<const ulonglong2*>(wrow);
            ulonglong2 wB = *reinterpret_cast<const ulonglong2*>(wrow + 4);
            #pragma unroll
            for (int r = 0; r < 8; r++) {
                uint32_t b = (kk < 2) ? xb[r].x : xb[r].y;
                uint32_t xbits = (kk & 1) ? (b & 0xFFFF0000u) : (b << 16);
                u64 xp = pack2(__uint_as_float(xbits));
                ffma2(acc[r][0], xp, wA.x);
                ffma2(acc[r][1], xp, wA.y);
                ffma2(acc[r][2], xp, wB.x);
                ffma2(acc[r][3], xp, wB.y);
            }
        }
    }

    #pragma unroll
    for (int r = 0; r < 8; r++) {
        int nd = row0 + rg + r;
        if (nd < nRows) {
            __half2 hv[4];
            #pragma unroll
            for (int c = 0; c < 4; c++) {
                float2 f = unpack2(acc[r][c]);
                hv[c] = __floats2half2_rn(f.x, f.y);
            }
            *reinterpret_cast<uint4*>(&out[(size_t)nd * (HDIM / 2) + tcol * 4]) =
                *reinterpret_cast<const uint4*>(hv);
        }
    }
}

// ---------------- aggregation core ------------------------------------------
__device__ __forceinline__ void agg_gather2(
    const __half2* __restrict__ tin, int* __restrict__ srcs,
    int node, int lane,
    float& a0x, float& a0y, float& a1x, float& a1y)
{
    int s0 = __ldg(&g_row_start[node]);
    int s1 = __ldg(&g_row_start[node + 1]);
    for (int base = s0; base < s1; base += 32) {
        int idx = base + lane;
        srcs[lane] = (idx < s1) ? __ldg(&g_csr_src[idx]) : 0;
        __syncwarp();
        int cnt = min(32, s1 - base);
        for (int j0 = 0; j0 < cnt; j0 += 8) {
            float2 v0[8], v1[8];
            #pragma unroll
            for (int jj = 0; jj < 8; jj++) {
                int s = srcs[j0 + jj];
                const __half2* p = tin + ((size_t)s * 2) * (HDIM / 2) + lane;
                v0[jj] = __half22float2(__ldg(p));
                v1[jj] = __half22float2(__ldg(p + (HDIM / 2)));
            }
            #pragma unroll
            for (int jj = 0; jj < 8; jj++) {
                if (j0 + jj < cnt) {
                    a0x += v0[jj].x; a0y += v0[jj].y;
                    a1x += v1[jj].x; a1y += v1[jj].y;
                }
            }
        }
        __syncwarp();
    }
}

// Layer-1 aggregation: writes bf16 rows with norm_src FOLDED IN (gemm2 input).
__global__ __launch_bounds__(256) void agg_kernel(
    const __half2* __restrict__ tin, __nv_bfloat16* __restrict__ tout,
    const float* __restrict__ b, int n)
{
    __shared__ int smem_srcs[8][32];
    int node = (blockIdx.x * blockDim.x + threadIdx.x) >> 5;
    int lane = threadIdx.x & 31;
    int wib  = threadIdx.x >> 5;
    if (node >= n) return;

    float a0x = 0.f, a0y = 0.f, a1x = 0.f, a1y = 0.f;
    agg_gather2(tin, smem_srcs[wib], node, lane, a0x, a0y, a1x, a1y);

    float nd = g_norm_dst[node];
    float ns = g_norm_src[node];
    float2 bb = *reinterpret_cast<const float2*>(b + lane * 2);
    __nv_bfloat162 o0 = __floats2bfloat162_rn(
        fmaxf(fmaf(a0x, nd, bb.x), 0.f) * ns, fmaxf(fmaf(a0y, nd, bb.y), 0.f) * ns);
    __nv_bfloat162 o1 = __floats2bfloat162_rn(
        fmaxf(fmaf(a1x, nd, bb.x), 0.f) * ns, fmaxf(fmaf(a1y, nd, bb.y), 0.f) * ns);
    __nv_bfloat16* r0 = tout + ((size_t)node * 2) * HDIM;
    *reinterpret_cast<__nv_bfloat162*>(r0 + lane * 2) = o0;
    *reinterpret_cast<__nv_bfloat162*>(r0 + HDIM + lane * 2) = o1;
}

// Layer-2 aggregation fused with scoring + loss (both encoders per warp).
__global__ __launch_bounds__(256) void agg_score_kernel(
    const __half2* __restrict__ tin, const float* __restrict__ b,
    const float* __restrict__ labels, int n)
{
    __shared__ int smem_srcs[8][32];
    __shared__ float sw[8];
    int node = (blockIdx.x * blockDim.x + threadIdx.x) >> 5;
    int lane = threadIdx.x & 31;
    int wib  = threadIdx.x >> 5;

    float term = 0.f;
    if (node < n) {
        float a0x = 0.f, a0y = 0.f, a1x = 0.f, a1y = 0.f;
        agg_gather2(tin, smem_srcs[wib], node, lane, a0x, a0y, a1x, a1y);

        float nd = g_norm_dst[node];
        float2 bb = *reinterpret_cast<const float2*>(b + lane * 2);
        float2 wv = *reinterpret_cast<const float2*>(&g_wv[lane * 2]);

        float o0x = fmaxf(fmaf(a0x, nd, bb.x), 0.f);
        float o0y = fmaxf(fmaf(a0y, nd, bb.y), 0.f);
        float o1x = fmaxf(fmaf(a1x, nd, bb.x), 0.f);
        float o1y = fmaxf(fmaf(a1y, nd, bb.y), 0.f);

        float p0 = o0x * wv.x + o0y * wv.y;
        float p1 = o1x * wv.x + o1y * wv.y;
        #pragma unroll
        for (int o = 16; o; o >>= 1) {
            p0 += __shfl_down_sync(0xffffffffu, p0, o);
            p1 += __shfl_down_sync(0xffffffffu, p1, o);
        }
        if (lane == 0) {
            float sc0 = p0 + g_bsum;
            float sc1 = p1 + g_bsum;
            float y0 = labels[node];
            float y1 = labels[(size_t)n + node];
            term = fmaxf(sc0, 0.f) + log1pf(expf(-fabsf(sc0))) - sc0 * y0
                 + fmaxf(sc1, 0.f) + log1pf(expf(-fabsf(sc1))) - sc1 * y1;
        }
    }
    if (lane == 0) sw[wib] = term;
    __syncthreads();
    if (threadIdx.x == 0) {
        float s = 0.f;
        #pragma unroll
        for (int w = 0; w < 8; w++) s += sw[w];
        atomicAdd(&g_loss, (double)s);
    }
}

__global__ void finalize_kernel(float* __restrict__ out, double inv) {
    out[0] = (float)(g_loss * inv);
}

// ---------------- launch -----------------------------------------------------
extern "C" void kernel_launch(void* const* d_in, const int* in_sizes, int n_in,
                              void* d_out, int out_size) {
    const float* features = (const float*)d_in[0];
    const float* labels   = (const float*)d_in[1];
    const float* W1 = (const float*)d_in[2];
    const float* b1 = (const float*)d_in[3];
    const float* W2 = (const float*)d_in[4];
    const float* b2 = (const float*)d_in[5];
    const float* Wm = (const float*)d_in[6];
    const float* bm = (const float*)d_in[7];
    const int* src  = (const int*)d_in[8];
    const int* dst  = (const int*)d_in[9];
    const int* perm = (const int*)d_in[10];

    int E = in_sizes[8];
    int n = in_sizes[10];

    __half2* bufA; __nv_bfloat16* bufB; float* nsrc;
    cudaGetSymbolAddress((void**)&bufA, g_bufAh);
    cudaGetSymbolAddress((void**)&bufB, g_bufBh);
    cudaGetSymbolAddress((void**)&nsrc, g_norm_src);

    const int SMEM1 = 256 * 136 * 2 + 128 * 68 * 4;   // 69,632 + 34,816 = 104,448 B
    const int SMEM2 = 256 * 72 * 2 + 64 * 68 * 4;     // 36,864 + 17,408 =  54,272 B
    cudaFuncSetAttribute(gemm1_kernel, cudaFuncAttributeMaxDynamicSharedMemorySize, SMEM1);
    cudaFuncSetAttribute(gemm2_kernel, cudaFuncAttributeMaxDynamicSharedMemorySize, SMEM2);

    int nb256  = (n + 255) / 256;
    int eb256  = (E + 255) / 256;
    int scanB  = (n + 1023) / 1024;
    dim3 gemm1G((n + 255) / 256, 2);
    int  gemm2B = (2 * n + 255) / 256;
    int  warpB  = (n + 7) / 8;

    // gemm1 kept 4th for the fixed-slot ncu capture.
    zero_kernel<<<nb256, 256>>>(n, E);
    degree_kernel<<<eb256, 256>>>(src, dst, E);
    norm_kernel<<<nb256, 256>>>(n);
    gemm1_kernel<<<gemm1G, 256, SMEM1>>>(features, W1, perm, nsrc, bufA, n);
    scan1_kernel<<<scanB, 256>>>(n);
    scan2_kernel<<<scanB, 256>>>(n);
    scatter_kernel<<<eb256, 256>>>(src, dst, E);
    wv_kernel<<<1, 64>>>(Wm, bm);

    agg_kernel<<<warpB, 256>>>(bufA, bufB, b1, n);
    gemm2_kernel<<<gemm2B, 256, SMEM2>>>(bufB, W2, bufA, 2 * n);
    agg_score_kernel<<<warpB, 256>>>(bufA, b2, labels, n);

    finalize_kernel<<<1, 1>>>((float*)d_out, 0.5 / (double)n);
}